// round 8
// baseline (speedup 1.0000x reference)
#include <cuda_runtime.h>
#include <cuda_bf16.h>
#include <cstdint>

#define B_   2
#define S_   2048
#define D_   1024
#define H_   16
#define DK_  64
#define BH_  (B_ * H_)
#define M_ROWS (B_ * S_)   // 4096

#define QSCALE 0.18033688011112042f   // log2(e)/sqrt(64)

// ---------------- scratch ----------------
__device__ __nv_bfloat16 g_Xhi[M_ROWS * D_];
__device__ __nv_bfloat16 g_Xlo[M_ROWS * D_];
__device__ __nv_bfloat16 g_Wth[3 * D_ * D_];
__device__ __nv_bfloat16 g_Wtl[3 * D_ * D_];
__device__ __nv_bfloat16 g_Qh[BH_ * S_ * DK_];
__device__ __nv_bfloat16 g_Ql[BH_ * S_ * DK_];
__device__ __nv_bfloat16 g_Kh[BH_ * S_ * DK_];
__device__ __nv_bfloat16 g_Kl[BH_ * S_ * DK_];
__device__ __nv_bfloat16 g_Vh[BH_ * S_ * DK_];
__device__ __nv_bfloat16 g_Vl[BH_ * S_ * DK_];

// ---------------- helpers ----------------
__device__ __forceinline__ uint32_t smem_u32(const void* p) {
    uint32_t a;
    asm("{ .reg .u64 t; cvta.to.shared.u64 t, %1; cvt.u32.u64 %0, t; }" : "=r"(a) : "l"(p));
    return a;
}
__device__ __forceinline__ void ldsm4(uint32_t* r, uint32_t addr) {
    asm volatile("ldmatrix.sync.aligned.m8n8.x4.shared.b16 {%0,%1,%2,%3}, [%4];"
        : "=r"(r[0]), "=r"(r[1]), "=r"(r[2]), "=r"(r[3]) : "r"(addr));
}
__device__ __forceinline__ void ldsm4t(uint32_t* r, uint32_t addr) {
    asm volatile("ldmatrix.sync.aligned.m8n8.x4.trans.shared.b16 {%0,%1,%2,%3}, [%4];"
        : "=r"(r[0]), "=r"(r[1]), "=r"(r[2]), "=r"(r[3]) : "r"(addr));
}
__device__ __forceinline__ void mma16816(float* c, const uint32_t* a, const uint32_t* b) {
    asm volatile("mma.sync.aligned.m16n8k16.row.col.f32.bf16.bf16.f32 "
        "{%0,%1,%2,%3}, {%4,%5,%6,%7}, {%8,%9}, {%0,%1,%2,%3};"
        : "+f"(c[0]), "+f"(c[1]), "+f"(c[2]), "+f"(c[3])
        : "r"(a[0]), "r"(a[1]), "r"(a[2]), "r"(a[3]), "r"(b[0]), "r"(b[1]));
}
__device__ __forceinline__ void cpa16(uint32_t d, const void* g) {
    asm volatile("cp.async.cg.shared.global [%0], [%1], 16;" :: "r"(d), "l"(g));
}
#define CP_COMMIT() asm volatile("cp.async.commit_group;" ::: "memory")
#define CP_WAIT0()  asm volatile("cp.async.wait_group 0;" ::: "memory")

// packed bf16 hi/lo split: 6 ops (cvt, shf, lop, 2x fadd, cvt)
__device__ __forceinline__ void split2(float a, float b, uint32_t& hi, uint32_t& lo) {
    uint32_t h;
    asm("cvt.rn.bf16x2.f32 %0, %1, %2;" : "=r"(h) : "f"(b), "f"(a));
    const float fa = __uint_as_float(h << 16);            // bf16(a) as f32 (exact)
    const float fb = __uint_as_float(h & 0xffff0000u);    // bf16(b) as f32 (exact)
    const float ra = a - fa, rb = b - fb;
    uint32_t l;
    asm("cvt.rn.bf16x2.f32 %0, %1, %2;" : "=r"(l) : "f"(rb), "f"(ra));
    hi = h; lo = l;
}

// ---------------------------------------------------------------------------
__global__ __launch_bounds__(256) void split_bf16(
    const float* __restrict__ src, __nv_bfloat16* __restrict__ hi,
    __nv_bfloat16* __restrict__ lo, int n4)
{
    int i = blockIdx.x * blockDim.x + threadIdx.x;
    if (i >= n4) return;
    float4 v = ((const float4*)src)[i];
    uint32_t h0, l0, h1, l1;
    split2(v.x, v.y, h0, l0);
    split2(v.z, v.w, h1, l1);
    uint2 hu = {h0, h1}, lu = {l0, l1};
    ((uint2*)hi)[i] = hu;
    ((uint2*)lo)[i] = lu;
}

// ---------------------------------------------------------------------------
__global__ void transpose_split(const float* __restrict__ W0,
                                const float* __restrict__ W1,
                                const float* __restrict__ W2,
                                __nv_bfloat16* __restrict__ hi,
                                __nv_bfloat16* __restrict__ lo)
{
    __shared__ float t[32][33];
    const float* W = (blockIdx.z == 0) ? W0 : (blockIdx.z == 1) ? W1 : W2;
    const int k = blockIdx.y * 32 + threadIdx.y;
    const int n = blockIdx.x * 32 + threadIdx.x;
    t[threadIdx.y][threadIdx.x] = W[(size_t)k * D_ + n];
    __syncthreads();
    const int nn = blockIdx.x * 32 + threadIdx.y + blockIdx.z * D_;
    const int kk = blockIdx.y * 32 + threadIdx.x;
    float v = t[threadIdx.x][threadIdx.y];
    __nv_bfloat16 h = __float2bfloat16(v);
    __nv_bfloat16 l = __float2bfloat16(v - __bfloat162float(h));
    hi[(size_t)nn * D_ + kk] = h;
    lo[(size_t)nn * D_ + kk] = l;
}

// ---------------------------------------------------------------------------
// HMMA GEMM: 2-stage cp.async prefetch-1, single barrier per slab, 2 CTAs/SM.
// Single fA/fB fragment buffers (Ah reloaded for pass 3) -> no spills at 128.
// ---------------------------------------------------------------------------
#define GROWB 80
#define SLABB (128 * GROWB)       // 10240
#define STAGEB (4 * SLABB)        // 40960
#define GSMEM (2 * STAGEB)        // 81920

__global__ __launch_bounds__(256, 2) void gemm_tc(
    const __nv_bfloat16* __restrict__ Ah, const __nv_bfloat16* __restrict__ Al,
    const __nv_bfloat16* __restrict__ Bh, const __nv_bfloat16* __restrict__ Bl,
    const float* __restrict__ b0, const float* __restrict__ b1,
    const float* __restrict__ b2, float* __restrict__ Yf,
    __nv_bfloat16* __restrict__ Qh, __nv_bfloat16* __restrict__ Ql,
    __nv_bfloat16* __restrict__ Kh, __nv_bfloat16* __restrict__ Kl,
    __nv_bfloat16* __restrict__ Vh, __nv_bfloat16* __restrict__ Vl,
    int mode)
{
    extern __shared__ __align__(16) unsigned char dsm[];
    const uint32_t s0 = smem_u32(dsm);

    const int tid = threadIdx.x, wid = tid >> 5, lane = tid & 31;
    const int wm = wid >> 2, wn = wid & 3;
    const int bm = blockIdx.y * 128, bn = blockIdx.x * 128;

    const int a4 = tid >> 6, t4 = tid & 63;
    const __nv_bfloat16* gsrc =
        (a4 == 0) ? Ah : (a4 == 1) ? Al : (a4 == 2) ? Bh : Bl;
    gsrc += (size_t)((a4 < 2) ? bm : bn) * 1024;
    const uint32_t slab = s0 + (uint32_t)a4 * SLABB;

    const uint32_t aRow = (uint32_t)(wm * 64 + (lane & 15));
    const uint32_t aCol = (uint32_t)(lane >> 4) * 16;
    const uint32_t bRow0 = (uint32_t)(wn * 32 + ((lane >> 4) & 1) * 8 + (lane & 7));
    const uint32_t bKoff = (uint32_t)((lane >> 3) & 1) * 16;

    float acc[16][4];
#pragma unroll
    for (int i = 0; i < 16; i++)
#pragma unroll
        for (int j = 0; j < 4; j++) acc[i][j] = 0.f;

    auto issue = [&](int ks) {
        const uint32_t st = slab + (uint32_t)(ks & 1) * STAGEB;
        const __nv_bfloat16* g = gsrc + ks * 32;
#pragma unroll
        for (int p = 0; p < 8; p++) {
            const int idx = p * 64 + t4;
            const int row = idx >> 2, ch = idx & 3;
            cpa16(st + (uint32_t)row * GROWB + (uint32_t)ch * 16,
                  g + (size_t)row * 1024 + ch * 8);
        }
        CP_COMMIT();
    };

    issue(0);

    for (int ks = 0; ks < 32; ks++) {
        CP_WAIT0();
        __syncthreads();
        if (ks + 1 < 32) issue(ks + 1);

        const uint32_t sb  = s0 + (uint32_t)(ks & 1) * STAGEB;
        const uint32_t SAh = sb, SAl = sb + SLABB;
        const uint32_t SBh = sb + 2 * SLABB, SBl = sb + 3 * SLABB;

#pragma unroll
        for (int h = 0; h < 2; h++) {
            uint32_t fA[4][4], fB[4][2];
            const uint32_t hoff = (uint32_t)h * 32;
            // Ah + Bh
#pragma unroll
            for (int mt = 0; mt < 4; mt++)
                ldsm4(fA[mt], SAh + (aRow + (uint32_t)(mt * 16)) * GROWB + hoff + aCol);
#pragma unroll
            for (int g = 0; g < 2; g++) {
                uint32_t r[4];
                ldsm4(r, SBh + (bRow0 + (uint32_t)(g * 16)) * GROWB + hoff + bKoff);
                fB[g * 2][0] = r[0]; fB[g * 2][1] = r[1];
                fB[g * 2 + 1][0] = r[2]; fB[g * 2 + 1][1] = r[3];
            }
            // pass 1: Ah x Bh
#pragma unroll
            for (int mt = 0; mt < 4; mt++)
#pragma unroll
                for (int nt = 0; nt < 4; nt++)
                    mma16816(acc[mt * 4 + nt], fA[mt], fB[nt]);
            // Al into fA; pass 2: Al x Bh
#pragma unroll
            for (int mt = 0; mt < 4; mt++)
                ldsm4(fA[mt], SAl + (aRow + (uint32_t)(mt * 16)) * GROWB + hoff + aCol);
#pragma unroll
            for (int mt = 0; mt < 4; mt++)
#pragma unroll
                for (int nt = 0; nt < 4; nt++)
                    mma16816(acc[mt * 4 + nt], fA[mt], fB[nt]);
            // Bl into fB; Ah reloaded into fA; pass 3: Ah x Bl
#pragma unroll
            for (int g = 0; g < 2; g++) {
                uint32_t r[4];
                ldsm4(r, SBl + (bRow0 + (uint32_t)(g * 16)) * GROWB + hoff + bKoff);
                fB[g * 2][0] = r[0]; fB[g * 2][1] = r[1];
                fB[g * 2 + 1][0] = r[2]; fB[g * 2 + 1][1] = r[3];
            }
#pragma unroll
            for (int mt = 0; mt < 4; mt++)
                ldsm4(fA[mt], SAh + (aRow + (uint32_t)(mt * 16)) * GROWB + hoff + aCol);
#pragma unroll
            for (int mt = 0; mt < 4; mt++)
#pragma unroll
                for (int nt = 0; nt < 4; nt++)
                    mma16816(acc[mt * 4 + nt], fA[mt], fB[nt]);
        }
    }

    // ---- epilogue ----
    const int qr = lane >> 2, qc = (lane & 3) * 2;
    const int proj = bn >> 10;
    const float* bias = (proj == 0) ? b0 : (proj == 1) ? b1 : b2;
    const float scale = (mode == 1 && proj == 0) ? QSCALE : 1.0f;
    __nv_bfloat16* Yh = (proj == 0) ? Qh : (proj == 1) ? Kh : Vh;
    __nv_bfloat16* Yl = (proj == 0) ? Ql : (proj == 1) ? Kl : Vl;
    const int bnl = bn & 1023;

#pragma unroll
    for (int mt = 0; mt < 4; mt++) {
#pragma unroll
        for (int nt = 0; nt < 4; nt++) {
            const float* a4p = acc[mt * 4 + nt];
            const int r0 = bm + wm * 64 + mt * 16 + qr;
            const int cn = bnl + wn * 32 + nt * 8 + qc;
            const float bv0 = bias[cn], bv1 = bias[cn + 1];
            if (mode == 0) {
                float2 v0 = {a4p[0] + bv0, a4p[1] + bv1};
                float2 v1 = {a4p[2] + bv0, a4p[3] + bv1};
                *(float2*)(Yf + (size_t)r0 * 1024 + cn) = v0;
                *(float2*)(Yf + (size_t)(r0 + 8) * 1024 + cn) = v1;
            } else {
                const float w0 = (a4p[0] + bv0) * scale, w1 = (a4p[1] + bv1) * scale;
                const float w2 = (a4p[2] + bv0) * scale, w3 = (a4p[3] + bv1) * scale;
                const int h  = cn >> 6, dk = cn & 63;
                const int b0i = r0 >> 11, s0i = r0 & 2047;
                const int b1i = (r0 + 8) >> 11, s1i = (r0 + 8) & 2047;
                const size_t o0 = (((size_t)(b0i * H_ + h)) * S_ + s0i) * DK_ + dk;
                const size_t o1 = (((size_t)(b1i * H_ + h)) * S_ + s1i) * DK_ + dk;
                uint32_t h0, l0, h1, l1;
                split2(w0, w1, h0, l0);
                split2(w2, w3, h1, l1);
                *(uint32_t*)(Yh + o0) = h0; *(uint32_t*)(Yl + o0) = l0;
                *(uint32_t*)(Yh + o1) = h1; *(uint32_t*)(Yl + o1) = l1;
            }
        }
    }
}

// ---------------------------------------------------------------------------
// Flash attention (causal): 128 threads / 64 q-rows per CTA, 2 CTAs/SM.
// Skip-rescale when running max unchanged; packed split2.
// ---------------------------------------------------------------------------
#define ASMEM 81920

__global__ __launch_bounds__(128, 2) void flash_attn_tc(
    const __nv_bfloat16* __restrict__ Qh, const __nv_bfloat16* __restrict__ Ql,
    const __nv_bfloat16* __restrict__ Kh, const __nv_bfloat16* __restrict__ Kl,
    const __nv_bfloat16* __restrict__ Vh, const __nv_bfloat16* __restrict__ Vl,
    __nv_bfloat16* __restrict__ Ohi, __nv_bfloat16* __restrict__ Olo)
{
    extern __shared__ __align__(16) unsigned char sm[];
    const uint32_t s0 = smem_u32(sm);

    const int tid = threadIdx.x, wid = tid >> 5, lane = tid & 31;
    const int qt = 31 - blockIdx.x;
    const int bh = blockIdx.y;
    const int qbase = qt * 64;
    const int njt = qt + 1;
    const int rb = wid * 16;

    {
        const int arr = tid >> 6;
        const int t2 = tid & 63;
        const __nv_bfloat16* base = (arr ? Ql : Qh) + ((size_t)bh * S_ + qbase) * DK_;
        const uint32_t db = (uint32_t)arr * 8192;
#pragma unroll
        for (int p = 0; p < 8; p++) {
            const int idx = p * 64 + t2;
            const int row = idx >> 3, ch = idx & 7;
            *(uint4*)(sm + db + (uint32_t)row * 128 + (uint32_t)((ch ^ (row & 7)) << 4)) =
                *(const uint4*)(base + (size_t)row * 64 + ch * 8);
        }
    }
    __syncthreads();

    uint32_t qfh[4][4], qfl[4][4];
    {
        const int row = rb + (lane & 15);
        const int r7 = row & 7;
#pragma unroll
        for (int kk = 0; kk < 4; kk++) {
            const uint32_t a = s0 + (uint32_t)row * 128 +
                (uint32_t)(((2 * kk + (lane >> 4)) ^ r7) << 4);
            ldsm4(qfh[kk], a);
            ldsm4(qfl[kk], a + 8192);
        }
    }
    __syncthreads();

    const int a4  = tid >> 5;
    const int t5  = tid & 31;
    const __nv_bfloat16* kvsrc =
        (a4 == 0) ? Kh : (a4 == 1) ? Kl : (a4 == 2) ? Vh : Vl;
    kvsrc += (size_t)bh * S_ * DK_;
    const uint32_t kvdst = s0 + 16384 + (uint32_t)a4 * 8192;

    {
        const __nv_bfloat16* g = kvsrc;
#pragma unroll
        for (int p = 0; p < 16; p++) {
            const int idx = p * 32 + t5;
            const int row = idx >> 3, ch = idx & 7;
            cpa16(kvdst + (uint32_t)row * 128 + (uint32_t)((ch ^ (row & 7)) << 4),
                  g + (size_t)row * 64 + ch * 8);
        }
    }
    CP_COMMIT();

    float m_i[2] = {-1e30f, -1e30f};
    float l_i[2] = {0.f, 0.f};
    float oac[8][4];
#pragma unroll
    for (int t = 0; t < 8; t++)
#pragma unroll
        for (int e = 0; e < 4; e++) oac[t][e] = 0.f;

    for (int jt = 0; jt < njt; jt++) {
        CP_WAIT0();
        __syncthreads();
        const uint32_t bb = s0 + 16384 + (uint32_t)(jt & 1) * 32768;

        if (jt + 1 < njt) {
            const __nv_bfloat16* g = kvsrc + (size_t)(jt + 1) * 64 * 64;
            const uint32_t db = kvdst + (uint32_t)((jt + 1) & 1) * 32768;
#pragma unroll
            for (int p = 0; p < 16; p++) {
                const int idx = p * 32 + t5;
                const int row = idx >> 3, ch = idx & 7;
                cpa16(db + (uint32_t)row * 128 + (uint32_t)((ch ^ (row & 7)) << 4),
                      g + (size_t)row * 64 + ch * 8);
            }
            CP_COMMIT();
        }

        float sc[8][4];
#pragma unroll
        for (int t = 0; t < 8; t++)
#pragma unroll
            for (int e = 0; e < 4; e++) sc[t][e] = 0.f;

#pragma unroll
        for (int kk = 0; kk < 4; kk++) {
#pragma unroll
            for (int j = 0; j < 4; j++) {
                const int krow = 16 * j + (lane & 7) + ((lane & 16) >> 1);
                const uint32_t ka = bb + (uint32_t)krow * 128 +
                    (uint32_t)(((2 * kk + ((lane >> 3) & 1)) ^ (krow & 7)) << 4);
                uint32_t bhf[4], blf[4];
                ldsm4(bhf, ka);
                ldsm4(blf, ka + 8192);
                mma16816(sc[2 * j],     qfh[kk], bhf + 0);
                mma16816(sc[2 * j + 1], qfh[kk], bhf + 2);
                mma16816(sc[2 * j],     qfh[kk], blf + 0);
                mma16816(sc[2 * j + 1], qfh[kk], blf + 2);
                mma16816(sc[2 * j],     qfl[kk], bhf + 0);
                mma16816(sc[2 * j + 1], qfl[kk], bhf + 2);
            }
        }

        if (jt == njt - 1) {
#pragma unroll
            for (int t = 0; t < 8; t++)
#pragma unroll
                for (int e = 0; e < 4; e++) {
                    const int kg = t * 8 + 2 * (lane & 3) + (e & 1);
                    const int qg = rb + (lane >> 2) + (e >> 1) * 8;
                    if (kg > qg) sc[t][e] = -1e9f;
                }
        }

#pragma unroll
        for (int h = 0; h < 2; h++) {
            float mr = -1e30f;
#pragma unroll
            for (int t = 0; t < 8; t++)
                mr = fmaxf(mr, fmaxf(sc[t][2 * h], sc[t][2 * h + 1]));
            mr = fmaxf(mr, __shfl_xor_sync(0xffffffffu, mr, 1));
            mr = fmaxf(mr, __shfl_xor_sync(0xffffffffu, mr, 2));
            const float mn = fmaxf(m_i[h], mr);
            // rescale only if some lane's running max grew (exact: alpha==1 otherwise)
            if (__any_sync(0xffffffffu, mn != m_i[h])) {
                const float alpha = exp2f(m_i[h] - mn);
                m_i[h] = mn;
                l_i[h] *= alpha;
#pragma unroll
                for (int t = 0; t < 8; t++) {
                    oac[t][2 * h]     *= alpha;
                    oac[t][2 * h + 1] *= alpha;
                }
            }
            float rs = 0.f;
#pragma unroll
            for (int t = 0; t < 8; t++) {
                sc[t][2 * h]     = exp2f(sc[t][2 * h] - mn);
                sc[t][2 * h + 1] = exp2f(sc[t][2 * h + 1] - mn);
                rs += sc[t][2 * h] + sc[t][2 * h + 1];
            }
            rs += __shfl_xor_sync(0xffffffffu, rs, 1);
            rs += __shfl_xor_sync(0xffffffffu, rs, 2);
            l_i[h] += rs;
        }

#pragma unroll
        for (int kk = 0; kk < 4; kk++) {
            uint32_t pah[4], pal[4];
            split2(sc[2 * kk][0],     sc[2 * kk][1],     pah[0], pal[0]);
            split2(sc[2 * kk][2],     sc[2 * kk][3],     pah[1], pal[1]);
            split2(sc[2 * kk + 1][0], sc[2 * kk + 1][1], pah[2], pal[2]);
            split2(sc[2 * kk + 1][2], sc[2 * kk + 1][3], pah[3], pal[3]);

            const int vrow = 16 * kk + (lane & 15);
            const int vr7 = vrow & 7;
#pragma unroll
            for (int j = 0; j < 4; j++) {
                const uint32_t va = bb + 16384 + (uint32_t)vrow * 128 +
                    (uint32_t)(((2 * j + (lane >> 4)) ^ vr7) << 4);
                uint32_t vhf[4], vlf[4];
                ldsm4t(vhf, va);
                ldsm4t(vlf, va + 8192);
                mma16816(oac[2 * j],     pah, vhf + 0);
                mma16816(oac[2 * j + 1], pah, vhf + 2);
                mma16816(oac[2 * j],     pah, vlf + 0);
                mma16816(oac[2 * j + 1], pah, vlf + 2);
                mma16816(oac[2 * j],     pal, vhf + 0);
                mma16816(oac[2 * j + 1], pal, vhf + 2);
            }
        }
    }

    const int bb_ = bh >> 4, hh = bh & 15;
#pragma unroll
    for (int h = 0; h < 2; h++) {
        const float invl = 1.f / l_i[h];
        const int rg = qbase + rb + (lane >> 2) + 8 * h;
        const size_t mrow = (size_t)(bb_ * 2048 + rg) * 1024;
#pragma unroll
        for (int t = 0; t < 8; t++) {
            const float v0 = oac[t][2 * h] * invl;
            const float v1 = oac[t][2 * h + 1] * invl;
            const int col = hh * 64 + t * 8 + 2 * (lane & 3);
            uint32_t hi, lo;
            split2(v0, v1, hi, lo);
            *(uint32_t*)(Ohi + mrow + col) = hi;
            *(uint32_t*)(Olo + mrow + col) = lo;
        }
    }
}

// ---------------------------------------------------------------------------
extern "C" void kernel_launch(void* const* d_in, const int* in_sizes, int n_in,
                              void* d_out, int out_size)
{
    const float* x  = (const float*)d_in[0];
    const float* Wq = (const float*)d_in[2];
    const float* bq = (const float*)d_in[3];
    const float* Wk = (const float*)d_in[4];
    const float* bk = (const float*)d_in[5];
    const float* Wv = (const float*)d_in[6];
    const float* bv = (const float*)d_in[7];
    const float* Wo = (const float*)d_in[8];
    const float* bo = (const float*)d_in[9];

    __nv_bfloat16 *xh, *xl, *wth, *wtl, *qh, *ql, *kh, *kl, *vh, *vl;
    cudaGetSymbolAddress((void**)&xh, g_Xhi);
    cudaGetSymbolAddress((void**)&xl, g_Xlo);
    cudaGetSymbolAddress((void**)&wth, g_Wth);
    cudaGetSymbolAddress((void**)&wtl, g_Wtl);
    cudaGetSymbolAddress((void**)&qh, g_Qh);
    cudaGetSymbolAddress((void**)&ql, g_Ql);
    cudaGetSymbolAddress((void**)&kh, g_Kh);
    cudaGetSymbolAddress((void**)&kl, g_Kl);
    cudaGetSymbolAddress((void**)&vh, g_Vh);
    cudaGetSymbolAddress((void**)&vl, g_Vl);

    const int n4 = M_ROWS * D_ / 4;
    const dim3 tb(32, 32);

    cudaFuncSetAttribute(gemm_tc, cudaFuncAttributeMaxDynamicSharedMemorySize, GSMEM);
    cudaFuncSetAttribute(flash_attn_tc, cudaFuncAttributeMaxDynamicSharedMemorySize, ASMEM);

    split_bf16<<<(n4 + 255) / 256, 256>>>(x, xh, xl, n4);
    transpose_split<<<dim3(32, 32, 3), tb>>>(Wq, Wk, Wv, wth, wtl);

    gemm_tc<<<dim3(24, 32), 256, GSMEM>>>(xh, xl, wth, wtl, bq, bk, bv,
                                          nullptr, qh, ql, kh, kl, vh, vl, 1);

    flash_attn_tc<<<dim3(32, BH_), 128, ASMEM>>>(qh, ql, kh, kl, vh, vl, xh, xl);

    transpose_split<<<dim3(32, 32, 1), tb>>>(Wo, Wo, Wo, wth, wtl);
    gemm_tc<<<dim3(8, 32), 256, GSMEM>>>(xh, xl, wth, wtl, bo, bo, bo,
                                         (float*)d_out, nullptr, nullptr,
                                         nullptr, nullptr, nullptr, nullptr, 0);
}